// round 8
// baseline (speedup 1.0000x reference)
#include <cuda_runtime.h>

#define B_ 2
#define N_ 1024
#define D_ 128
#define H_ 64

// Scratch (no allocations allowed): intermediate projections.
__device__ float g_ai[B_ * N_ * H_];    // [b][n][h]
__device__ float g_ajbT[B_ * H_ * N_];  // [b][h][n]  (aj + b1, transposed)

// ---------------------------------------------------------------------------
// Pass 1: ai = E @ Wi^T ; ajbT = (E @ Wj^T + b1) transposed to [h][n].
// Block = 256 threads, 8 rows of E (r = tid>>5 warp-uniform -> Esh read is a
// pure broadcast; ob = (tid&31)*4 -> conflict-free LDS.128 on Wc). Grid = 256.
// ---------------------------------------------------------------------------
__global__ __launch_bounds__(256) void pass1_kernel(
    const float* __restrict__ E, const float* __restrict__ W1,
    const float* __restrict__ b1)
{
    __shared__ float Esh[8][32];
    __shared__ float Wc[32][132];   // padded: 4-way STS conflicts max, rows 16B-aligned

    const int tid = threadIdx.x;
    const int r = tid >> 5;
    const int ob = (tid & 31) * 4;
    const int row0 = blockIdx.x * 8;

    float acc[4] = {0.f, 0.f, 0.f, 0.f};

    for (int dc = 0; dc < D_; dc += 32) {
        __syncthreads();
        {   // Stage 8x32 chunk of E (coalesced, one elem per thread).
            int rr = tid >> 5, dd = tid & 31;
            Esh[rr][dd] = E[(row0 + rr) * D_ + dc + dd];
        }
        // Stage W chunk, coalesced LDG (consecutive lanes -> consecutive dd).
#pragma unroll
        for (int k = tid; k < 32 * 128; k += 256) {
            int o = k >> 5, dd = k & 31;
            float v = (o < H_) ? W1[o * (2 * D_) + dc + dd]
                               : W1[(o - H_) * (2 * D_) + D_ + dc + dd];
            Wc[dd][o] = v;
        }
        __syncthreads();
#pragma unroll
        for (int dd = 0; dd < 32; dd++) {
            const float e = Esh[r][dd];                     // warp broadcast
            const float4 w4 = *(const float4*)&Wc[dd][ob];  // conflict-free
            acc[0] += e * w4.x;  acc[1] += e * w4.y;
            acc[2] += e * w4.z;  acc[3] += e * w4.w;
        }
    }

    const int row = row0 + r;            // row = b*N + n
    if (ob < H_) {
        *(float4*)&g_ai[row * H_ + ob] = make_float4(acc[0], acc[1], acc[2], acc[3]);
    } else {
        const int b = row >> 10;
        const int n = row & (N_ - 1);
        const int h0 = ob - H_;
#pragma unroll
        for (int k = 0; k < 4; k++)
            g_ajbT[(b * H_ + h0 + k) * N_ + n] = acc[k] + b1[h0 + k];
    }
}

// ---------------------------------------------------------------------------
// Pass 2: fused edge weights + mask + softmax + write, with visited-row skip.
// If visited[i] is true the WHOLE row is masked -> softmax is exactly
// uniform 1/N: write it directly, no compute (warp-uniform, ~50% of rows).
// Grid = B * N/8 = 256 blocks, 128 threads = 4 warps; warp w owns rows
// i0 = i_base + 2w, i0+1. Scalar math (packed f32x2 regressed in R7).
// ---------------------------------------------------------------------------
__global__ __launch_bounds__(128, 4) void pass2_kernel(
    const int* __restrict__ visited,
    const float* __restrict__ W2, const float* __restrict__ b2,
    float* __restrict__ out)
{
    __shared__ float ajb[H_][128];          // 32 KB
    __shared__ float4 comb[4][H_];          // 4 KB: (ai_row0, ai_row1, w2, 0)
    __shared__ int vis_sh[N_];              // 4 KB

    const int tid = threadIdx.x;
    const int w = tid >> 5, lane = tid & 31;
    const int b = blockIdx.x >> 7;
    const int i_base = (blockIdx.x & 127) * 8;
    const int i0 = i_base + 2 * w;
    const int i1 = i0 + 1;

#pragma unroll
    for (int k = tid; k < 4 * H_; k += 128) {
        int wi = k >> 6, h = k & 63;
        int ii = i_base + 2 * wi;
        comb[wi][h] = make_float4(g_ai[(b * N_ + ii) * H_ + h],
                                  g_ai[(b * N_ + ii + 1) * H_ + h],
                                  W2[h], 0.f);
    }
#pragma unroll
    for (int k = tid; k < N_; k += 128) vis_sh[k] = visited[b * N_ + k];
    __syncthreads();

    const bool vi0 = vis_sh[i0] != 0;       // warp-uniform
    const bool vi1 = vis_sh[i1] != 0;
    const int nact = (vi0 ? 0 : 1) + (vi1 ? 0 : 1);

    // Visited rows: softmax over all -1e9 == exactly uniform 1/N.
    const float4 uni = make_float4(1.f / N_, 1.f / N_, 1.f / N_, 1.f / N_);
    if (vi0) {
        float* orow = out + (size_t)(b * N_ + i0) * N_;
#pragma unroll
        for (int t = 0; t < 8; t++) *(float4*)&orow[t * 128 + lane * 4] = uni;
    }
    if (vi1) {
        float* orow = out + (size_t)(b * N_ + i1) * N_;
#pragma unroll
        for (int t = 0; t < 8; t++) *(float4*)&orow[t * 128 + lane * 4] = uni;
    }

    float a0[8][4], a1[8][4];

#pragma unroll
    for (int t = 0; t < 8; t++) {
        __syncthreads();
#pragma unroll
        for (int k = tid; k < H_ * 32; k += 128) {
            int h = k >> 5, c4 = k & 31;
            *(float4*)&ajb[h][c4 * 4] =
                *(const float4*)&g_ajbT[(b * H_ + h) * N_ + t * 128 + c4 * 4];
        }
        __syncthreads();

        if (nact == 2) {
            float s00 = 0.f, s01 = 0.f, s02 = 0.f, s03 = 0.f;
            float s10 = 0.f, s11 = 0.f, s12 = 0.f, s13 = 0.f;
#pragma unroll 8
            for (int h = 0; h < H_; h++) {
                const float4 c = comb[w][h];                  // LDS.128 bcast
                const float4 v = *(const float4*)&ajb[h][lane * 4];
                s00 += fmaxf(c.x + v.x, 0.f) * c.z;
                s01 += fmaxf(c.x + v.y, 0.f) * c.z;
                s02 += fmaxf(c.x + v.z, 0.f) * c.z;
                s03 += fmaxf(c.x + v.w, 0.f) * c.z;
                s10 += fmaxf(c.y + v.x, 0.f) * c.z;
                s11 += fmaxf(c.y + v.y, 0.f) * c.z;
                s12 += fmaxf(c.y + v.z, 0.f) * c.z;
                s13 += fmaxf(c.y + v.w, 0.f) * c.z;
            }
            a0[t][0] = s00; a0[t][1] = s01; a0[t][2] = s02; a0[t][3] = s03;
            a1[t][0] = s10; a1[t][1] = s11; a1[t][2] = s12; a1[t][3] = s13;
        } else if (nact == 1) {
            // Single active row computed into a0.
            float s0 = 0.f, s1 = 0.f, s2 = 0.f, s3 = 0.f;
#pragma unroll 8
            for (int h = 0; h < H_; h++) {
                const float4 c = comb[w][h];
                const float a = vi0 ? c.y : c.x;              // uniform SEL
                const float4 v = *(const float4*)&ajb[h][lane * 4];
                s0 += fmaxf(a + v.x, 0.f) * c.z;
                s1 += fmaxf(a + v.y, 0.f) * c.z;
                s2 += fmaxf(a + v.z, 0.f) * c.z;
                s3 += fmaxf(a + v.w, 0.f) * c.z;
            }
            a0[t][0] = s0; a0[t][1] = s1; a0[t][2] = s2; a0[t][3] = s3;
        }
    }

    if (nact == 0) return;

    // ---- mask + softmax for active rows (in registers, warp-wide) ----
    const float bb = b2[0];
    const int ia = vi0 ? i1 : i0;           // row held in a0
    {
        float m = -3.4e38f;
#pragma unroll
        for (int t = 0; t < 8; t++)
#pragma unroll
            for (int k = 0; k < 4; k++) {
                const int j = t * 128 + lane * 4 + k;
                float e = (vis_sh[j] != 0) ? -1.0e9f : (a0[t][k] + bb);
                a0[t][k] = e;
                m = fmaxf(m, e);
            }
#pragma unroll
        for (int o = 16; o > 0; o >>= 1)
            m = fmaxf(m, __shfl_xor_sync(0xffffffffu, m, o));
        float sum = 0.f;
#pragma unroll
        for (int t = 0; t < 8; t++)
#pragma unroll
            for (int k = 0; k < 4; k++) {
                const float p = __expf(a0[t][k] - m);
                a0[t][k] = p; sum += p;
            }
#pragma unroll
        for (int o = 16; o > 0; o >>= 1)
            sum += __shfl_xor_sync(0xffffffffu, sum, o);
        const float inv = 1.f / sum;
        float* orow = out + (size_t)(b * N_ + ia) * N_;
#pragma unroll
        for (int t = 0; t < 8; t++)
            *(float4*)&orow[t * 128 + lane * 4] =
                make_float4(a0[t][0] * inv, a0[t][1] * inv,
                            a0[t][2] * inv, a0[t][3] * inv);
    }

    if (nact == 2) {                        // second active row (i1) in a1
        float m = -3.4e38f;
#pragma unroll
        for (int t = 0; t < 8; t++)
#pragma unroll
            for (int k = 0; k < 4; k++) {
                const int j = t * 128 + lane * 4 + k;
                float e = (vis_sh[j] != 0) ? -1.0e9f : (a1[t][k] + bb);
                a1[t][k] = e;
                m = fmaxf(m, e);
            }
#pragma unroll
        for (int o = 16; o > 0; o >>= 1)
            m = fmaxf(m, __shfl_xor_sync(0xffffffffu, m, o));
        float sum = 0.f;
#pragma unroll
        for (int t = 0; t < 8; t++)
#pragma unroll
            for (int k = 0; k < 4; k++) {
                const float p = __expf(a1[t][k] - m);
                a1[t][k] = p; sum += p;
            }
#pragma unroll
        for (int o = 16; o > 0; o >>= 1)
            sum += __shfl_xor_sync(0xffffffffu, sum, o);
        const float inv = 1.f / sum;
        float* orow = out + (size_t)(b * N_ + i1) * N_;
#pragma unroll
        for (int t = 0; t < 8; t++)
            *(float4*)&orow[t * 128 + lane * 4] =
                make_float4(a1[t][0] * inv, a1[t][1] * inv,
                            a1[t][2] * inv, a1[t][3] * inv);
    }
}

extern "C" void kernel_launch(void* const* d_in, const int* in_sizes, int n_in,
                              void* d_out, int out_size) {
    const float* E  = (const float*)d_in[0];
    const int* vis  = (const int*)d_in[1];   // jax bool -> int32 in harness
    // d_in[2] = remaining_capacity: unused by the reference.
    const float* W1 = (const float*)d_in[3];
    const float* b1 = (const float*)d_in[4];
    const float* W2 = (const float*)d_in[5];
    const float* b2 = (const float*)d_in[6];
    float* out      = (float*)d_out;

    pass1_kernel<<<256, 256>>>(E, W1, b1);
    pass2_kernel<<<256, 128>>>(vis, W2, b2, out);
}

// round 11
// speedup vs baseline: 1.0517x; 1.0517x over previous
#include <cuda_runtime.h>

#define B_ 2
#define N_ 1024
#define D_ 128
#define H_ 64

// Scratch (no allocations allowed): intermediate projections.
__device__ float g_ai[B_ * N_ * H_];    // [b][n][h]
__device__ float g_ajbT[B_ * H_ * N_];  // [b][h][n]  (aj + b1, transposed)

// ---------------------------------------------------------------------------
// Pass 1: ai = E @ Wi^T ; ajbT = (E @ Wj^T + b1) transposed to [h][n].
// Block = 256 threads, 8 rows of E (r = tid>>5 warp-uniform -> Esh read is a
// pure broadcast; ob = (tid&31)*4 -> conflict-free LDS.128 on Wc). Grid = 256.
// ---------------------------------------------------------------------------
__global__ __launch_bounds__(256) void pass1_kernel(
    const float* __restrict__ E, const float* __restrict__ W1,
    const float* __restrict__ b1)
{
    __shared__ float Esh[8][32];
    __shared__ float Wc[32][132];   // padded: 4-way STS conflicts max, rows 16B-aligned

    const int tid = threadIdx.x;
    const int r = tid >> 5;
    const int ob = (tid & 31) * 4;
    const int row0 = blockIdx.x * 8;

    float acc[4] = {0.f, 0.f, 0.f, 0.f};

    for (int dc = 0; dc < D_; dc += 32) {
        __syncthreads();
        {   // Stage 8x32 chunk of E (coalesced, one elem per thread).
            int rr = tid >> 5, dd = tid & 31;
            Esh[rr][dd] = E[(row0 + rr) * D_ + dc + dd];
        }
        // Stage W chunk, coalesced LDG (consecutive lanes -> consecutive dd).
#pragma unroll
        for (int k = tid; k < 32 * 128; k += 256) {
            int o = k >> 5, dd = k & 31;
            float v = (o < H_) ? W1[o * (2 * D_) + dc + dd]
                               : W1[(o - H_) * (2 * D_) + D_ + dc + dd];
            Wc[dd][o] = v;
        }
        __syncthreads();
#pragma unroll
        for (int dd = 0; dd < 32; dd++) {
            const float e = Esh[r][dd];                     // warp broadcast
            const float4 w4 = *(const float4*)&Wc[dd][ob];  // conflict-free
            acc[0] += e * w4.x;  acc[1] += e * w4.y;
            acc[2] += e * w4.z;  acc[3] += e * w4.w;
        }
    }

    const int row = row0 + r;            // row = b*N + n
    if (ob < H_) {
        *(float4*)&g_ai[row * H_ + ob] = make_float4(acc[0], acc[1], acc[2], acc[3]);
    } else {
        const int b = row >> 10;
        const int n = row & (N_ - 1);
        const int h0 = ob - H_;
#pragma unroll
        for (int k = 0; k < 4; k++)
            g_ajbT[(b * H_ + h0 + k) * N_ + n] = acc[k] + b1[h0 + k];
    }
}

// ---------------------------------------------------------------------------
// Pass 2: fused edge weights + mask + softmax + write.
// Grid = B * N/8 = 256 blocks, 256 threads = 8 warps; warp w owns ONE row
// i = i_base + w. 3 CTAs/SM resident (launch_bounds(256,3), ~60 regs) so a
// visited-skipped warp's issue slots are pooled by active warps of
// co-resident CTAs (the R8 skip failure mode). Visited rows -> exact uniform
// 1/N written directly; skipped warps still run the staging/barrier skeleton.
// (ai, w2) pre-packed as float2 -> 1 LDS.64 broadcast per h.
// ---------------------------------------------------------------------------
__global__ __launch_bounds__(256, 3) void pass2_kernel(
    const int* __restrict__ visited,
    const float* __restrict__ W2, const float* __restrict__ b2,
    float* __restrict__ out)
{
    __shared__ float ajb[H_][128];          // 32 KB
    __shared__ float2 pk[8][H_];            // 4 KB: (ai[i], w2[h]) per (warp,h)
    __shared__ int vis_sh[N_];              // 4 KB

    const int tid = threadIdx.x;
    const int w = tid >> 5, lane = tid & 31;
    const int b = blockIdx.x >> 7;
    const int i_base = (blockIdx.x & 127) * 8;
    const int i = i_base + w;

#pragma unroll
    for (int k = tid; k < 8 * H_; k += 256) {
        int wi = k >> 6, h = k & 63;
        pk[wi][h] = make_float2(g_ai[(b * N_ + i_base + wi) * H_ + h], W2[h]);
    }
#pragma unroll
    for (int k = tid; k < N_; k += 256) vis_sh[k] = visited[b * N_ + k];
    __syncthreads();

    const bool vi = vis_sh[i] != 0;         // warp-uniform

    if (vi) {
        // Whole row masked -> softmax exactly uniform 1/N. Write now; keep
        // running the t-loop skeleton below (barriers must stay convergent).
        const float4 uni = make_float4(1.f / N_, 1.f / N_, 1.f / N_, 1.f / N_);
        float* orow = out + (size_t)(b * N_ + i) * N_;
#pragma unroll
        for (int t = 0; t < 8; t++) *(float4*)&orow[t * 128 + lane * 4] = uni;
    }

    float a[8][4];

#pragma unroll
    for (int t = 0; t < 8; t++) {
        __syncthreads();
#pragma unroll
        for (int k = tid; k < H_ * 32; k += 256) {
            int h = k >> 5, c4 = k & 31;
            *(float4*)&ajb[h][c4 * 4] =
                *(const float4*)&g_ajbT[(b * H_ + h) * N_ + t * 128 + c4 * 4];
        }
        __syncthreads();

        if (!vi) {
            float s0 = 0.f, s1 = 0.f, s2 = 0.f, s3 = 0.f;
#pragma unroll 8
            for (int h = 0; h < H_; h++) {
                const float2 c = pk[w][h];                    // LDS.64 bcast
                const float4 v = *(const float4*)&ajb[h][lane * 4];
                s0 += fmaxf(c.x + v.x, 0.f) * c.y;
                s1 += fmaxf(c.x + v.y, 0.f) * c.y;
                s2 += fmaxf(c.x + v.z, 0.f) * c.y;
                s3 += fmaxf(c.x + v.w, 0.f) * c.y;
            }
            a[t][0] = s0; a[t][1] = s1; a[t][2] = s2; a[t][3] = s3;
        }
    }

    if (vi) return;

    // ---- mask + softmax (in registers, warp-wide) ----
    const float bb = b2[0];
    float m = -3.4e38f;
#pragma unroll
    for (int t = 0; t < 8; t++)
#pragma unroll
        for (int k = 0; k < 4; k++) {
            const int j = t * 128 + lane * 4 + k;
            float e = (vis_sh[j] != 0) ? -1.0e9f : (a[t][k] + bb);
            a[t][k] = e;
            m = fmaxf(m, e);
        }
#pragma unroll
    for (int o = 16; o > 0; o >>= 1)
        m = fmaxf(m, __shfl_xor_sync(0xffffffffu, m, o));

    float sum = 0.f;
#pragma unroll
    for (int t = 0; t < 8; t++)
#pragma unroll
        for (int k = 0; k < 4; k++) {
            const float p = __expf(a[t][k] - m);
            a[t][k] = p; sum += p;
        }
#pragma unroll
    for (int o = 16; o > 0; o >>= 1)
        sum += __shfl_xor_sync(0xffffffffu, sum, o);

    const float inv = 1.f / sum;
    float* orow = out + (size_t)(b * N_ + i) * N_;
#pragma unroll
    for (int t = 0; t < 8; t++)
        *(float4*)&orow[t * 128 + lane * 4] =
            make_float4(a[t][0] * inv, a[t][1] * inv,
                        a[t][2] * inv, a[t][3] * inv);
}

extern "C" void kernel_launch(void* const* d_in, const int* in_sizes, int n_in,
                              void* d_out, int out_size) {
    const float* E  = (const float*)d_in[0];
    const int* vis  = (const int*)d_in[1];   // jax bool -> int32 in harness
    // d_in[2] = remaining_capacity: unused by the reference.
    const float* W1 = (const float*)d_in[3];
    const float* b1 = (const float*)d_in[4];
    const float* W2 = (const float*)d_in[5];
    const float* b2 = (const float*)d_in[6];
    float* out      = (float*)d_out;

    pass1_kernel<<<256, 256>>>(E, W1, b1);
    pass2_kernel<<<256, 256>>>(vis, W2, b2, out);
}

// round 12
// speedup vs baseline: 1.1165x; 1.0617x over previous
#include <cuda_runtime.h>

#define B_ 2
#define N_ 1024
#define D_ 128
#define H_ 64

// Scratch (no allocations allowed).
__device__ float g_ai[B_ * N_ * H_];     // [b][n][h]
__device__ float g_ajbT[B_ * H_ * N_];   // [b][h][n]  (aj + b1, transposed)
__device__ float g_ajbTc[B_ * H_ * N_];  // [b][h][jc] column-compacted (active j only)
__device__ int   g_jlist[B_ * N_];       // [b][jc] -> original j
__device__ int   g_nact[B_];             // active column count per batch

// ---------------------------------------------------------------------------
// Pass 1: ai = E @ Wi^T ; ajbT = (E @ Wj^T + b1) transposed to [h][n].
// (unchanged — proven)
// ---------------------------------------------------------------------------
__global__ __launch_bounds__(256) void pass1_kernel(
    const float* __restrict__ E, const float* __restrict__ W1,
    const float* __restrict__ b1)
{
    __shared__ float Esh[8][32];
    __shared__ float Wc[32][132];

    const int tid = threadIdx.x;
    const int r = tid >> 5;
    const int ob = (tid & 31) * 4;
    const int row0 = blockIdx.x * 8;

    float acc[4] = {0.f, 0.f, 0.f, 0.f};

    for (int dc = 0; dc < D_; dc += 32) {
        __syncthreads();
        {
            int rr = tid >> 5, dd = tid & 31;
            Esh[rr][dd] = E[(row0 + rr) * D_ + dc + dd];
        }
#pragma unroll
        for (int k = tid; k < 32 * 128; k += 256) {
            int o = k >> 5, dd = k & 31;
            float v = (o < H_) ? W1[o * (2 * D_) + dc + dd]
                               : W1[(o - H_) * (2 * D_) + D_ + dc + dd];
            Wc[dd][o] = v;
        }
        __syncthreads();
#pragma unroll
        for (int dd = 0; dd < 32; dd++) {
            const float e = Esh[r][dd];
            const float4 w4 = *(const float4*)&Wc[dd][ob];
            acc[0] += e * w4.x;  acc[1] += e * w4.y;
            acc[2] += e * w4.z;  acc[3] += e * w4.w;
        }
    }

    const int row = row0 + r;
    if (ob < H_) {
        *(float4*)&g_ai[row * H_ + ob] = make_float4(acc[0], acc[1], acc[2], acc[3]);
    } else {
        const int b = row >> 10;
        const int n = row & (N_ - 1);
        const int h0 = ob - H_;
#pragma unroll
        for (int k = 0; k < 4; k++)
            g_ajbT[(b * H_ + h0 + k) * N_ + n] = acc[k] + b1[h0 + k];
    }
}

// ---------------------------------------------------------------------------
// Compact: jlist[b][.] = ascending list of j with visited[b][j]==0; nact[b].
// Grid = B_, 1024 threads. Ballot + warp-scan of warp totals.
// ---------------------------------------------------------------------------
__global__ __launch_bounds__(1024) void compact_kernel(const int* __restrict__ visited)
{
    __shared__ int warpTot[32], warpOff[32];
    const int b = blockIdx.x;
    const int tid = threadIdx.x;
    const int lane = tid & 31, w = tid >> 5;

    const bool act = (visited[b * N_ + tid] == 0);
    const unsigned mask = __ballot_sync(0xffffffffu, act);
    const int rank = __popc(mask & ((1u << lane) - 1u));
    if (lane == 0) warpTot[w] = __popc(mask);
    __syncthreads();
    if (w == 0) {
        int v = warpTot[lane];
        int s = v;
#pragma unroll
        for (int o = 1; o < 32; o <<= 1) {
            int x = __shfl_up_sync(0xffffffffu, s, o);
            if (lane >= o) s += x;
        }
        warpOff[lane] = s - v;                 // exclusive prefix
        if (lane == 31) g_nact[b] = s;
    }
    __syncthreads();
    if (act) g_jlist[b * N_ + warpOff[w] + rank] = tid;
}

// ---------------------------------------------------------------------------
// Gather: ajbTc[b][h][jc] = ajbT[b][h][jlist[jc]], zero-padded to 128-mult.
// Grid = B_*H_ = 128 blocks, 128 threads. Source row is 4KB -> L1-resident.
// ---------------------------------------------------------------------------
__global__ __launch_bounds__(128) void gather_kernel()
{
    const int b = blockIdx.x >> 6;
    const int h = blockIdx.x & 63;
    const int tid = threadIdx.x;
    const int nact = g_nact[b];
    const int npad = (nact + 127) & ~127;
    const float* src = &g_ajbT[(b * H_ + h) * N_];
    float* dst = &g_ajbTc[(b * H_ + h) * N_];
    const int* jl = &g_jlist[b * N_];
    for (int jc = tid; jc < npad; jc += 128)
        dst[jc] = (jc < nact) ? src[jl[jc]] : 0.f;
}

// ---------------------------------------------------------------------------
// Pass 2 over COMPACTED columns. Grid = B_*N_/4 = 512 blocks, 128 thr =
// 4 warps, warp w owns row i = i_base + w. T = ceil(nact/128) tiles (~4)
// instead of 8; block-uniform t<T guard inside static loop keeps acc in regs
// and barriers convergent. Visited row -> uniform 1/N. Active row -> zero the
// full row, compute softmax over active columns only (masked entries are
// exactly 0 in the reference: expf(-1e9-m) underflows to +0), scatter via
// jlist. Ordering zero->scatter is guaranteed by the intervening
// __syncthreads (block-scope memory fence).
// ---------------------------------------------------------------------------
__global__ __launch_bounds__(128) void pass2_kernel(
    const int* __restrict__ visited,
    const float* __restrict__ W2, const float* __restrict__ b2,
    float* __restrict__ out)
{
    __shared__ float ajb[H_][128];          // 32 KB
    __shared__ float2 pk[4][H_];            // 2 KB: (ai[i], w2[h])
    __shared__ int jl_sh[N_];               // 4 KB

    const int tid = threadIdx.x;
    const int w = tid >> 5, lane = tid & 31;
    const int b = blockIdx.x >> 8;
    const int i_base = (blockIdx.x & 255) * 4;
    const int i = i_base + w;

    const int nact = g_nact[b];
    const int T = (nact + 127) >> 7;

#pragma unroll
    for (int k = tid; k < 4 * H_; k += 128) {
        int wi = k >> 6, h = k & 63;
        pk[wi][h] = make_float2(g_ai[(b * N_ + i_base + wi) * H_ + h], W2[h]);
    }
    for (int k = tid; k < nact; k += 128) jl_sh[k] = g_jlist[b * N_ + k];

    const bool vi = visited[b * N_ + i] != 0;   // warp-uniform
    float* orow = out + (size_t)(b * N_ + i) * N_;
    if (vi) {
        const float4 uni = make_float4(1.f / N_, 1.f / N_, 1.f / N_, 1.f / N_);
#pragma unroll
        for (int t = 0; t < 8; t++) *(float4*)&orow[t * 128 + lane * 4] = uni;
    } else {
        const float4 z = make_float4(0.f, 0.f, 0.f, 0.f);
#pragma unroll
        for (int t = 0; t < 8; t++) *(float4*)&orow[t * 128 + lane * 4] = z;
    }

    float a[8][4] = {};

#pragma unroll
    for (int t = 0; t < 8; t++) {
        if (t < T) {                            // block-uniform
            __syncthreads();
#pragma unroll
            for (int k = tid; k < H_ * 32; k += 128) {
                int h = k >> 5, c4 = k & 31;
                *(float4*)&ajb[h][c4 * 4] =
                    *(const float4*)&g_ajbTc[(b * H_ + h) * N_ + t * 128 + c4 * 4];
            }
            __syncthreads();

            if (!vi) {
                float s0 = 0.f, s1 = 0.f, s2 = 0.f, s3 = 0.f;
#pragma unroll 8
                for (int h = 0; h < H_; h++) {
                    const float2 c = pk[w][h];                 // LDS.64 bcast
                    const float4 v = *(const float4*)&ajb[h][lane * 4];
                    s0 += fmaxf(c.x + v.x, 0.f) * c.y;
                    s1 += fmaxf(c.x + v.y, 0.f) * c.y;
                    s2 += fmaxf(c.x + v.z, 0.f) * c.y;
                    s3 += fmaxf(c.x + v.w, 0.f) * c.y;
                }
                a[t][0] = s0; a[t][1] = s1; a[t][2] = s2; a[t][3] = s3;
            }
        }
    }

    if (vi) return;

    // ---- softmax over active columns (jc < nact), in registers ----
    const float bb = b2[0];
    float m = -3.4e38f;
#pragma unroll
    for (int t = 0; t < 8; t++)
#pragma unroll
        for (int k = 0; k < 4; k++) {
            const int jc = t * 128 + lane * 4 + k;
            float e = (jc < nact) ? (a[t][k] + bb) : -1.0e9f;
            a[t][k] = e;
            m = fmaxf(m, e);
        }
#pragma unroll
    for (int o = 16; o > 0; o >>= 1)
        m = fmaxf(m, __shfl_xor_sync(0xffffffffu, m, o));

    float sum = 0.f;
#pragma unroll
    for (int t = 0; t < 8; t++)
#pragma unroll
        for (int k = 0; k < 4; k++) {
            const float p = __expf(a[t][k] - m);
            a[t][k] = p; sum += p;
        }
#pragma unroll
    for (int o = 16; o > 0; o >>= 1)
        sum += __shfl_xor_sync(0xffffffffu, sum, o);

    const float inv = 1.f / sum;
#pragma unroll
    for (int t = 0; t < 8; t++)
#pragma unroll
        for (int k = 0; k < 4; k++) {
            const int jc = t * 128 + lane * 4 + k;
            if (jc < nact) orow[jl_sh[jc]] = a[t][k] * inv;
        }
}

extern "C" void kernel_launch(void* const* d_in, const int* in_sizes, int n_in,
                              void* d_out, int out_size) {
    const float* E  = (const float*)d_in[0];
    const int* vis  = (const int*)d_in[1];   // jax bool -> int32 in harness
    // d_in[2] = remaining_capacity: unused by the reference.
    const float* W1 = (const float*)d_in[3];
    const float* b1 = (const float*)d_in[4];
    const float* W2 = (const float*)d_in[5];
    const float* b2 = (const float*)d_in[6];
    float* out      = (float*)d_out;

    pass1_kernel<<<256, 256>>>(E, W1, b1);
    compact_kernel<<<B_, 1024>>>(vis);
    gather_kernel<<<B_ * H_, 128>>>();
    pass2_kernel<<<B_ * (N_ / 4), 128>>>(vis, W2, b2, out);
}